// round 16
// baseline (speedup 1.0000x reference)
#include <cuda_runtime.h>

// Problem constants (fixed by the reference setup)
#define NN 262144
#define EE 4194304
#define HID 32
#define LYR 4
#define FULLM 0xffffffffu

typedef unsigned long long ull;

// packed f32x2 helpers (sm_103a)
#define ADDX2(out, a, b) \
    asm("add.rn.f32x2 %0, %1, %2;" : "=l"(out) : "l"(a), "l"(b))
#define MULX2(out, a, b) \
    asm("mul.rn.f32x2 %0, %1, %2;" : "=l"(out) : "l"(a), "l"(b))
#define FMAX2(out, a, b, c) \
    asm("fma.rn.f32x2 %0, %1, %2, %3;" : "=l"(out) : "l"(a), "l"(b), "l"(c))
#define PACKX2(out, lo, hi) \
    asm("mov.b64 %0, {%1, %2};" : "=l"(out) : "f"(lo), "f"(hi))
#define UNPACKX2(lo, hi, in) \
    asm("mov.b64 {%0, %1}, %2;" : "=f"(lo), "=f"(hi) : "l"(in))

// ---------------- device scratch (static, no allocation) ----------------
__device__ int   g_deg[NN];        // zeroed at module load; re-zeroed by k_scan
__device__ int   g_cursor[NN];     // block-local offsets; after fill: local ends
__device__ int   g_blocksum[256];
__device__ int   g_boff[256];      // exclusive prefix of block sums
__device__ int   g_tick;           // last-block ticket (reset each run)
__device__ int   g_csr[EE];
__device__ __align__(16) float g_agg[NN * 32];
__device__ __align__(16) float g_z[NN * 32];
__device__ __align__(16) float g_hA[NN * 32];
__device__ __align__(16) float g_hB[NN * 32];
__device__ __align__(16) float g_acc[NN * 8];
__device__ float g_stats[LYR * 64];
__device__ float g_statsP[64];     // probe scratch (values unused)

// ---------------- #0: degree histogram ----------------
__global__ void k_hist(const int* __restrict__ ei) {
    int e = blockIdx.x * blockDim.x + threadIdx.x;
    if (e < EE) atomicAdd(&g_deg[ei[EE + e]], 1);
}

// ---------------- #1: fused two-level scan (last-block pattern) ----------
__global__ void k_scan() {
    __shared__ int wt[32];
    __shared__ int s_tot;
    __shared__ bool s_last;
    int tid = threadIdx.x, lane = tid & 31, wid = tid >> 5;
    int g = blockIdx.x * 1024 + tid;
    int v = g_deg[g];
    g_deg[g] = 0;
    int xv = v;
#pragma unroll
    for (int off = 1; off < 32; off <<= 1) {
        int y = __shfl_up_sync(FULLM, xv, off);
        if (lane >= off) xv += y;
    }
    if (lane == 31) wt[wid] = xv;
    __syncthreads();
    if (wid == 0) {
        int w = wt[lane];
        int xi = w;
#pragma unroll
        for (int off = 1; off < 32; off <<= 1) {
            int y = __shfl_up_sync(FULLM, xi, off);
            if (lane >= off) xi += y;
        }
        wt[lane] = xi - w;
        if (lane == 31) s_tot = xi;
    }
    __syncthreads();
    g_cursor[g] = (xv - v) + wt[wid];

    if (tid == 0) {
        g_blocksum[blockIdx.x] = s_tot;
        __threadfence();
        s_last = (atomicAdd(&g_tick, 1) == 255);
    }
    __syncthreads();
    if (s_last) {
        __shared__ int wt2[8];
        int bv = (tid < 256) ? g_blocksum[tid] : 0;
        int xi = bv;
#pragma unroll
        for (int off = 1; off < 32; off <<= 1) {
            int y = __shfl_up_sync(FULLM, xi, off);
            if (lane >= off) xi += y;
        }
        if (tid < 256 && lane == 31) wt2[wid] = xi;
        __syncthreads();
        if (tid == 0) {
            int s = 0;
            for (int k = 0; k < 8; k++) { int t0 = wt2[k]; wt2[k] = s; s += t0; }
        }
        __syncthreads();
        if (tid < 256) {
            g_boff[tid] = (xi - bv) + wt2[wid];
            g_stats[tid] = 0.f;
            if (tid < 64) g_statsP[tid] = 0.f;
        }
        if (tid == 0) g_tick = 0;
    }
}

// ---------------- #2: CSR fill ----------------
__global__ void k_fill(const int* __restrict__ ei) {
    int e = blockIdx.x * blockDim.x + threadIdx.x;
    if (e < EE) {
        int d = ei[EE + e];
        int p = __ldg(&g_boff[d >> 10]) + atomicAdd(&g_cursor[d], 1);
        g_csr[p] = ei[e];
    }
}

// ---------------- layer-0 aggregation (32B x-rows) ------------------------
__global__ __launch_bounds__(256) void k_agg0(
    const float* __restrict__ x, float* __restrict__ agg_out,
    const float* __restrict__ eps_p, const float* __restrict__ tptr)
{
    float epsv = 1.0f + eps_p[0];
    ull epsv2; PACKX2(epsv2, epsv, epsv);
    float tv = tptr[0];
    int tid = threadIdx.x, lane = tid & 31, wid = tid >> 5;
    int g = lane >> 1;               // node sub-index 0..15
    int r = lane & 1;                // 16B slot within 32B row
    int w  = blockIdx.x * (blockDim.x >> 5) + wid;
    int nw = gridDim.x * (blockDim.x >> 5);
    const ulonglong2* x2 = (const ulonglong2*)x;
    ulonglong2* agg2 = (ulonglong2*)agg_out;

    for (int tile = w; tile < NN / 16; tile += nw) {
        int i = tile * 16 + g;
        int bo = __ldg(&g_boff[i >> 10]);
        int le = g_cursor[i];
        int ls = (i & 1023) ? g_cursor[i - 1] : 0;
        int start = bo + ls;
        int deg = le - ls;

        int md = deg;
#pragma unroll
        for (int off = 16; off >= 2; off >>= 1)
            md = max(md, __shfl_xor_sync(FULLM, md, off));

        ull A0 = 0ull, A1 = 0ull, B0 = 0ull, B1 = 0ull;
        for (int j = 0; j < md; j += 2) {
            bool p0 = (j < deg), p1 = (j + 1 < deg);
            int s0 = 0, s1 = 0;
            if (p0) s0 = __ldg(&g_csr[start + j]);
            if (p1) s1 = __ldg(&g_csr[start + j + 1]);
            ull v0x = 0ull, v0y = 0ull, v1x = 0ull, v1y = 0ull;
            if (p0) { ulonglong2 v = __ldg(&x2[s0 * 2 + r]); v0x = v.x; v0y = v.y; }
            if (p1) { ulonglong2 v = __ldg(&x2[s1 * 2 + r]); v1x = v.x; v1y = v.y; }
            ADDX2(A0, A0, v0x); ADDX2(A1, A1, v0y);
            ADDX2(B0, B0, v1x); ADDX2(B1, B1, v1y);
        }
        ADDX2(A0, A0, B0);
        ADDX2(A1, A1, B1);
        ulonglong2 sf = __ldg(&x2[i * 2 + r]);
        FMAX2(A0, sf.x, epsv2, A0);
        FMAX2(A1, sf.y, epsv2, A1);
        ulonglong2 res; res.x = A0; res.y = A1;
        agg2[i * 4 + r] = res;
        float tt = (epsv + (float)deg) * tv;
        ulonglong2 pad;
        if (r == 0) { PACKX2(pad.x, tt, 0.f); } else { pad.x = 0ull; }
        pad.y = 0ull;
        agg2[i * 4 + 2 + r] = pad;
    }
}

// ---------------- aggregation for layers 1..3 (128B rows) -----------------
__global__ __launch_bounds__(256) void k_agg(
    const float* __restrict__ h_in, float* __restrict__ agg_out,
    const float* __restrict__ eps_p, int layer)
{
    float epsv = 1.0f + eps_p[layer];
    ull epsv2; PACKX2(epsv2, epsv, epsv);

    int tid = threadIdx.x, lane = tid & 31, wid = tid >> 5;
    int g = lane >> 3;               // node sub-index 0..3
    int r = lane & 7;                // 16B slot within 128B row
    int w  = blockIdx.x * (blockDim.x >> 5) + wid;
    int nw = gridDim.x * (blockDim.x >> 5);

    const ulonglong2* hin2 = (const ulonglong2*)h_in;
    ulonglong2* agg2 = (ulonglong2*)agg_out;

    for (int tile = w; tile < NN / 4; tile += nw) {
        int i = tile * 4 + g;
        int bo = __ldg(&g_boff[i >> 10]);
        int le = g_cursor[i];
        int ls = (i & 1023) ? g_cursor[i - 1] : 0;
        int start = bo + ls;
        int deg = le - ls;

        int md = deg;
#pragma unroll
        for (int off = 16; off >= 8; off >>= 1)
            md = max(md, __shfl_xor_sync(FULLM, md, off));

        ull A0 = 0ull, A1 = 0ull, B0 = 0ull, B1 = 0ull;
        for (int j = 0; j < md; j += 2) {
            bool p0 = (j < deg), p1 = (j + 1 < deg);
            int s0 = 0, s1 = 0;
            if (p0) s0 = __ldg(&g_csr[start + j]);
            if (p1) s1 = __ldg(&g_csr[start + j + 1]);
            ull v0x = 0ull, v0y = 0ull, v1x = 0ull, v1y = 0ull;
            if (p0) { ulonglong2 v = __ldg(&hin2[s0 * 8 + r]); v0x = v.x; v0y = v.y; }
            if (p1) { ulonglong2 v = __ldg(&hin2[s1 * 8 + r]); v1x = v.x; v1y = v.y; }
            ADDX2(A0, A0, v0x); ADDX2(A1, A1, v0y);
            ADDX2(B0, B0, v1x); ADDX2(B1, B1, v1y);
        }
        ADDX2(A0, A0, B0);
        ADDX2(A1, A1, B1);
        ulonglong2 sf = __ldg(&hin2[i * 8 + r]);
        FMAX2(A0, sf.x, epsv2, A0);
        FMAX2(A1, sf.y, epsv2, A1);
        ulonglong2 res; res.x = A0; res.y = A1;
        agg2[i * 8 + r] = res;
    }
}

// ---------------- MLP + BN stats: z = relu(agg@W1+b1)@W2+b2 -----------------
// Weights live in SMEM as pre-packed f32x2 pairs (low register pressure ->
// high occupancy). w1s/w2s layout: pair q, lane -> [q*32+lane], 8B stride
// across lanes (conflict-free LDS.64).
template <int STRIDE>
__global__ __launch_bounds__(256) void k_mlp(
    const float* __restrict__ agg, float* __restrict__ z_out,
    const float* __restrict__ W1, int w1rows, const float* __restrict__ b1,
    const float* __restrict__ W2, const float* __restrict__ b2,
    float* __restrict__ stats)
{
    constexpr int NP1 = STRIDE / 2;        // W1 pairs
    __shared__ ull w1s[NP1 * 32];
    __shared__ ull w2s[16 * 32];
    __shared__ float b1s[32], b2s[32];
    __shared__ __align__(16) float hs[8][32];
    __shared__ float rs[8][32], rq[8][32];

    int tid = threadIdx.x;
    int lane = tid & 31, wid = tid >> 5;

    for (int p = tid; p < NP1 * 32; p += 256) {
        int q = p >> 5, l = p & 31;
        float a = (2 * q     < w1rows) ? __ldg(&W1[(2 * q) * 32 + l])     : 0.f;
        float b = (2 * q + 1 < w1rows) ? __ldg(&W1[(2 * q + 1) * 32 + l]) : 0.f;
        ull pk; PACKX2(pk, a, b);
        w1s[p] = pk;
    }
    for (int p = tid; p < 16 * 32; p += 256) {
        int q = p >> 5, l = p & 31;
        float a = __ldg(&W2[(2 * q) * 32 + l]);
        float b = __ldg(&W2[(2 * q + 1) * 32 + l]);
        ull pk; PACKX2(pk, a, b);
        w2s[p] = pk;
    }
    if (tid < 32) { b1s[tid] = __ldg(&b1[tid]); b2s[tid] = __ldg(&b2[tid]); }
    __syncthreads();

    float b1v = b1s[lane];
    float b2v = b2s[lane];

    int w  = blockIdx.x * (blockDim.x >> 5) + wid;
    int nw = gridDim.x * (blockDim.x >> 5);
    float ssum = 0.f, ssq = 0.f;

    const ulonglong2* agg2 = (const ulonglong2*)agg;

    for (int i = w; i < NN; i += nw) {
        ull hp0 = 0ull, hp1 = 0ull;
#pragma unroll
        for (int q = 0; q < STRIDE / 4; q++) {
            ulonglong2 a = __ldg(&agg2[i * (STRIDE / 4) + q]);
            ull wA = w1s[(2 * q) * 32 + lane];
            ull wB = w1s[(2 * q + 1) * 32 + lane];
            FMAX2(hp0, a.x, wA, hp0);
            FMAX2(hp1, a.y, wB, hp1);
        }
        ADDX2(hp0, hp0, hp1);
        float lo, hi; UNPACKX2(lo, hi, hp0);
        float hid = fmaxf(b1v + lo + hi, 0.f);

        hs[wid][lane] = hid;
        __syncwarp();
        ull op0 = 0ull, op1 = 0ull;
        const ulonglong2* hrow = (const ulonglong2*)&hs[wid][0];
#pragma unroll
        for (int q = 0; q < 8; q++) {
            ulonglong2 hq = hrow[q];
            ull wA = w2s[(2 * q) * 32 + lane];
            ull wB = w2s[(2 * q + 1) * 32 + lane];
            FMAX2(op0, hq.x, wA, op0);
            FMAX2(op1, hq.y, wB, op1);
        }
        __syncwarp();
        ADDX2(op0, op0, op1);
        float ol, oh; UNPACKX2(ol, oh, op0);
        float o = b2v + ol + oh;
        z_out[i * 32 + lane] = o;
        ssum += o;
        ssq  = fmaf(o, o, ssq);
    }

    rs[wid][lane] = ssum;
    rq[wid][lane] = ssq;
    __syncthreads();
    if (wid == 0) {
        float s = 0.f, q = 0.f;
#pragma unroll
        for (int ww = 0; ww < 8; ww++) { s += rs[ww][lane]; q += rq[ww][lane]; }
        atomicAdd(&stats[lane], s);
        atomicAdd(&stats[32 + lane], q);
    }
}

// ---------------- BN apply + ReLU + incremental final linear (layers 0-2) --
__global__ __launch_bounds__(256) void k_bn(
    const float* __restrict__ z, float* __restrict__ h_out,
    const float* __restrict__ gamma, const float* __restrict__ beta,
    const float* __restrict__ linW, const float* __restrict__ lin_b,
    int layer)
{
    __shared__ float sc[32], bi[32];
    __shared__ __align__(16) float hsm[8][32];
    int tid = threadIdx.x;
    int lane = tid & 31, wid = tid >> 5;
    if (tid < 32) {
        float s = g_stats[layer * 64 + tid];
        float q = g_stats[layer * 64 + 32 + tid];
        float mu  = s * (1.0f / NN);
        float var = q * (1.0f / NN) - mu * mu;
        float inv = rsqrtf(var + 1e-5f);
        float g = gamma[layer * 32 + tid] * inv;
        sc[tid] = g;
        bi[tid] = beta[layer * 32 + tid] - mu * g;
    }
    int myd = lane & 7;
    ull lwp[16];
#pragma unroll
    for (int c = 0; c < 32; c += 2) {
        float a = __ldg(&linW[layer * 256 + c * 8 + myd]);
        float b = __ldg(&linW[layer * 256 + (c + 1) * 8 + myd]);
        PACKX2(lwp[c / 2], a, b);
    }
    float lbv = __ldg(&lin_b[myd]);
    __syncthreads();

    int w  = blockIdx.x * (blockDim.x >> 5) + wid;
    int nw = gridDim.x * (blockDim.x >> 5);
    for (int i = w; i < NN; i += nw) {
        float zv = z[i * 32 + lane];
        float h = fmaxf(fmaf(zv, sc[lane], bi[lane]), 0.f);
        h_out[i * 32 + lane] = h;
        hsm[wid][lane] = h;
        __syncwarp();
        ull op0 = 0ull, op1 = 0ull;
        const ulonglong2* hrow = (const ulonglong2*)&hsm[wid][0];
#pragma unroll
        for (int q = 0; q < 8; q++) {
            ulonglong2 hq = hrow[q];
            FMAX2(op0, hq.x, lwp[2 * q + 0], op0);
            FMAX2(op1, hq.y, lwp[2 * q + 1], op1);
        }
        __syncwarp();
        ADDX2(op0, op0, op1);
        float ol, oh; UNPACKX2(ol, oh, op0);
        float v = ol + oh;
        if (lane < 8) {
            if (layer == 0) v += lbv;
            else            v += g_acc[i * 8 + lane];
            g_acc[i * 8 + lane] = v;
        }
    }
}

// ---------------- final BN (layer 3) + masked write-back -------------------
__global__ __launch_bounds__(256) void k_bn_final(
    const float* __restrict__ z,
    const float* __restrict__ gamma, const float* __restrict__ beta,
    const float* __restrict__ linW,
    const float* __restrict__ x,
    const int* __restrict__ nm, const int* __restrict__ em,
    float* __restrict__ out)
{
    const int layer = 3;
    __shared__ float sc[32], bi[32];
    __shared__ __align__(16) float hsm[8][32];
    int tid = threadIdx.x;
    int lane = tid & 31, wid = tid >> 5;
    if (tid < 32) {
        float s = g_stats[layer * 64 + tid];
        float q = g_stats[layer * 64 + 32 + tid];
        float mu  = s * (1.0f / NN);
        float var = q * (1.0f / NN) - mu * mu;
        float inv = rsqrtf(var + 1e-5f);
        float g = gamma[layer * 32 + tid] * inv;
        sc[tid] = g;
        bi[tid] = beta[layer * 32 + tid] - mu * g;
    }
    int myd = lane & 7;
    ull lwp[16];
#pragma unroll
    for (int c = 0; c < 32; c += 2) {
        float a = __ldg(&linW[layer * 256 + c * 8 + myd]);
        float b = __ldg(&linW[layer * 256 + (c + 1) * 8 + myd]);
        PACKX2(lwp[c / 2], a, b);
    }
    __syncthreads();

    int w  = blockIdx.x * (blockDim.x >> 5) + wid;
    int nw = gridDim.x * (blockDim.x >> 5);
    for (int i = w; i < NN; i += nw) {
        float zv = z[i * 32 + lane];
        float h = fmaxf(fmaf(zv, sc[lane], bi[lane]), 0.f);
        hsm[wid][lane] = h;
        __syncwarp();
        ull op0 = 0ull, op1 = 0ull;
        const ulonglong2* hrow = (const ulonglong2*)&hsm[wid][0];
#pragma unroll
        for (int q = 0; q < 8; q++) {
            ulonglong2 hq = hrow[q];
            FMAX2(op0, hq.x, lwp[2 * q + 0], op0);
            FMAX2(op1, hq.y, lwp[2 * q + 1], op1);
        }
        __syncwarp();
        ADDX2(op0, op0, op1);
        float ol, oh; UNPACKX2(ol, oh, op0);
        if (lane < 8) {
            float v = (ol + oh) + g_acc[i * 8 + lane];
            bool n = (nm[i] != 0), e = (em[i] != 0);
            int c = lane;
            bool wr = (c >= 1) && ((c <= 4 && (n || e)) || (c == 5 && n));
            out[i * 8 + c] = wr ? v : __ldg(&x[i * 8 + c]);
        }
    }
}

// ---------------- launch ----------------
extern "C" void kernel_launch(void* const* d_in, const int* in_sizes, int n_in,
                              void* d_out, int out_size)
{
    const float* x        = (const float*)d_in[0];
    const float* t        = (const float*)d_in[1];
    const int*   ei       = (const int*)d_in[2];
    const int*   node_mask = (const int*)d_in[3];
    const int*   edge_mask = (const int*)d_in[4];
    const float* W1_first = (const float*)d_in[7];
    const float* b1_first = (const float*)d_in[8];
    const float* W2_first = (const float*)d_in[9];
    const float* b2_first = (const float*)d_in[10];
    const float* W1_rest  = (const float*)d_in[11];
    const float* b1_rest  = (const float*)d_in[12];
    const float* W2_rest  = (const float*)d_in[13];
    const float* b2_rest  = (const float*)d_in[14];
    const float* eps      = (const float*)d_in[15];
    const float* bn_gamma = (const float*)d_in[16];
    const float* bn_beta  = (const float*)d_in[17];
    const float* lin_W    = (const float*)d_in[18];
    const float* lin_b    = (const float*)d_in[19];
    float* out = (float*)d_out;

    const int GB = 148 * 8;

    float* ag; cudaGetSymbolAddress((void**)&ag, g_agg);
    float* zz; cudaGetSymbolAddress((void**)&zz, g_z);
    float* hA; cudaGetSymbolAddress((void**)&hA, g_hA);
    float* hB; cudaGetSymbolAddress((void**)&hB, g_hB);
    float* st; cudaGetSymbolAddress((void**)&st, g_stats);
    float* sp; cudaGetSymbolAddress((void**)&sp, g_statsP);

    k_hist<<<(EE + 255) / 256, 256>>>(ei);            // #0
    k_scan<<<256, 1024>>>();                          // #1
    k_fill<<<(EE + 255) / 256, 256>>>(ei);            // #2
    // #3 (ncu capture slot): PROBE of the NEW smem-weight k_mlp (stale g_agg,
    // scratch outputs) — verifies the occupancy fix in-round.
    k_mlp<32><<<GB, 256>>>(ag, zz, W1_rest + 2 * 1024, 32, b1_rest + 2 * 32,
                           W2_rest + 2 * 1024, b2_rest + 2 * 32, sp);

    // Layer 0
    k_agg0<<<GB, 256>>>(x, ag, eps, t);
    k_mlp<16><<<GB, 256>>>(ag, zz, W1_first, 9, b1_first, W2_first, b2_first, st + 0);
    k_bn<<<GB, 256>>>(zz, hA, bn_gamma, bn_beta, lin_W, lin_b, 0);

    // Layer 1
    k_agg<<<GB, 256>>>(hA, ag, eps, 1);
    k_mlp<32><<<GB, 256>>>(ag, zz, W1_rest + 0 * 1024, 32, b1_rest + 0 * 32,
                           W2_rest + 0 * 1024, b2_rest + 0 * 32, st + 64);
    k_bn<<<GB, 256>>>(zz, hB, bn_gamma, bn_beta, lin_W, lin_b, 1);

    // Layer 2
    k_agg<<<GB, 256>>>(hB, ag, eps, 2);
    k_mlp<32><<<GB, 256>>>(ag, zz, W1_rest + 1 * 1024, 32, b1_rest + 1 * 32,
                           W2_rest + 1 * 1024, b2_rest + 1 * 32, st + 128);
    k_bn<<<GB, 256>>>(zz, hA, bn_gamma, bn_beta, lin_W, lin_b, 2);

    // Layer 3 (bn fused with masked write-back)
    k_agg<<<GB, 256>>>(hA, ag, eps, 3);
    k_mlp<32><<<GB, 256>>>(ag, zz, W1_rest + 2 * 1024, 32, b1_rest + 2 * 32,
                           W2_rest + 2 * 1024, b2_rest + 2 * 32, st + 192);
    k_bn_final<<<GB, 256>>>(zz, bn_gamma, bn_beta, lin_W, x,
                            node_mask, edge_mask, out);
}

// round 17
// speedup vs baseline: 1.3236x; 1.3236x over previous
#include <cuda_runtime.h>

// Problem constants (fixed by the reference setup)
#define NN 262144
#define EE 4194304
#define HID 32
#define LYR 4
#define FULLM 0xffffffffu

typedef unsigned long long ull;

// packed f32x2 helpers (sm_103a)
#define ADDX2(out, a, b) \
    asm("add.rn.f32x2 %0, %1, %2;" : "=l"(out) : "l"(a), "l"(b))
#define MULX2(out, a, b) \
    asm("mul.rn.f32x2 %0, %1, %2;" : "=l"(out) : "l"(a), "l"(b))
#define FMAX2(out, a, b, c) \
    asm("fma.rn.f32x2 %0, %1, %2, %3;" : "=l"(out) : "l"(a), "l"(b), "l"(c))
#define PACKX2(out, lo, hi) \
    asm("mov.b64 %0, {%1, %2};" : "=l"(out) : "f"(lo), "f"(hi))
#define UNPACKX2(lo, hi, in) \
    asm("mov.b64 {%0, %1}, %2;" : "=f"(lo), "=f"(hi) : "l"(in))

// ---------------- device scratch (static, no allocation) ----------------
__device__ int   g_deg[NN];        // zeroed at module load; re-zeroed by k_scan
__device__ int   g_cursor[NN];     // block-local offsets; after fill: local ends
__device__ int   g_blocksum[256];
__device__ int   g_boff[256];      // exclusive prefix of block sums
__device__ int   g_tick;           // last-block ticket (reset each run)
__device__ int   g_csr[EE];
__device__ __align__(16) float g_agg[NN * 32];
__device__ __align__(16) float g_z[NN * 32];
__device__ __align__(16) float g_hA[NN * 32];
__device__ __align__(16) float g_hB[NN * 32];
__device__ __align__(16) float g_acc[NN * 8];
__device__ float g_stats[LYR * 64];
__device__ float g_statsP[64];     // probe scratch (values unused)

// ---------------- #0: degree histogram ----------------
__global__ void k_hist(const int* __restrict__ ei) {
    int e = blockIdx.x * blockDim.x + threadIdx.x;
    if (e < EE) atomicAdd(&g_deg[ei[EE + e]], 1);
}

// ---------------- #1: fused two-level scan (last-block pattern) ----------
__global__ void k_scan() {
    __shared__ int wt[32];
    __shared__ int s_tot;
    __shared__ bool s_last;
    int tid = threadIdx.x, lane = tid & 31, wid = tid >> 5;
    int g = blockIdx.x * 1024 + tid;
    int v = g_deg[g];
    g_deg[g] = 0;
    int xv = v;
#pragma unroll
    for (int off = 1; off < 32; off <<= 1) {
        int y = __shfl_up_sync(FULLM, xv, off);
        if (lane >= off) xv += y;
    }
    if (lane == 31) wt[wid] = xv;
    __syncthreads();
    if (wid == 0) {
        int w = wt[lane];
        int xi = w;
#pragma unroll
        for (int off = 1; off < 32; off <<= 1) {
            int y = __shfl_up_sync(FULLM, xi, off);
            if (lane >= off) xi += y;
        }
        wt[lane] = xi - w;
        if (lane == 31) s_tot = xi;
    }
    __syncthreads();
    g_cursor[g] = (xv - v) + wt[wid];

    if (tid == 0) {
        g_blocksum[blockIdx.x] = s_tot;
        __threadfence();
        s_last = (atomicAdd(&g_tick, 1) == 255);
    }
    __syncthreads();
    if (s_last) {
        __shared__ int wt2[8];
        int bv = (tid < 256) ? g_blocksum[tid] : 0;
        int xi = bv;
#pragma unroll
        for (int off = 1; off < 32; off <<= 1) {
            int y = __shfl_up_sync(FULLM, xi, off);
            if (lane >= off) xi += y;
        }
        if (tid < 256 && lane == 31) wt2[wid] = xi;
        __syncthreads();
        if (tid == 0) {
            int s = 0;
            for (int k = 0; k < 8; k++) { int t0 = wt2[k]; wt2[k] = s; s += t0; }
        }
        __syncthreads();
        if (tid < 256) {
            g_boff[tid] = (xi - bv) + wt2[wid];
            g_stats[tid] = 0.f;
            if (tid < 64) g_statsP[tid] = 0.f;
        }
        if (tid == 0) g_tick = 0;
    }
}

// ---------------- #2: CSR fill ----------------
__global__ void k_fill(const int* __restrict__ ei) {
    int e = blockIdx.x * blockDim.x + threadIdx.x;
    if (e < EE) {
        int d = ei[EE + e];
        int p = __ldg(&g_boff[d >> 10]) + atomicAdd(&g_cursor[d], 1);
        g_csr[p] = ei[e];
    }
}

// ---------------- layer-0 aggregation (32B x-rows) ------------------------
__global__ __launch_bounds__(256) void k_agg0(
    const float* __restrict__ x, float* __restrict__ agg_out,
    const float* __restrict__ eps_p, const float* __restrict__ tptr)
{
    float epsv = 1.0f + eps_p[0];
    ull epsv2; PACKX2(epsv2, epsv, epsv);
    float tv = tptr[0];
    int tid = threadIdx.x, lane = tid & 31, wid = tid >> 5;
    int g = lane >> 1;               // node sub-index 0..15
    int r = lane & 1;                // 16B slot within 32B row
    int w  = blockIdx.x * (blockDim.x >> 5) + wid;
    int nw = gridDim.x * (blockDim.x >> 5);
    const ulonglong2* x2 = (const ulonglong2*)x;
    ulonglong2* agg2 = (ulonglong2*)agg_out;

    for (int tile = w; tile < NN / 16; tile += nw) {
        int i = tile * 16 + g;
        int bo = __ldg(&g_boff[i >> 10]);
        int le = g_cursor[i];
        int ls = (i & 1023) ? g_cursor[i - 1] : 0;
        int start = bo + ls;
        int deg = le - ls;

        int md = deg;
#pragma unroll
        for (int off = 16; off >= 2; off >>= 1)
            md = max(md, __shfl_xor_sync(FULLM, md, off));

        ull A0 = 0ull, A1 = 0ull, B0 = 0ull, B1 = 0ull;
        for (int j = 0; j < md; j += 2) {
            bool p0 = (j < deg), p1 = (j + 1 < deg);
            int s0 = 0, s1 = 0;
            if (p0) s0 = __ldg(&g_csr[start + j]);
            if (p1) s1 = __ldg(&g_csr[start + j + 1]);
            ull v0x = 0ull, v0y = 0ull, v1x = 0ull, v1y = 0ull;
            if (p0) { ulonglong2 v = __ldg(&x2[s0 * 2 + r]); v0x = v.x; v0y = v.y; }
            if (p1) { ulonglong2 v = __ldg(&x2[s1 * 2 + r]); v1x = v.x; v1y = v.y; }
            ADDX2(A0, A0, v0x); ADDX2(A1, A1, v0y);
            ADDX2(B0, B0, v1x); ADDX2(B1, B1, v1y);
        }
        ADDX2(A0, A0, B0);
        ADDX2(A1, A1, B1);
        ulonglong2 sf = __ldg(&x2[i * 2 + r]);
        FMAX2(A0, sf.x, epsv2, A0);
        FMAX2(A1, sf.y, epsv2, A1);
        ulonglong2 res; res.x = A0; res.y = A1;
        agg2[i * 4 + r] = res;
        float tt = (epsv + (float)deg) * tv;
        ulonglong2 pad;
        if (r == 0) { PACKX2(pad.x, tt, 0.f); } else { pad.x = 0ull; }
        pad.y = 0ull;
        agg2[i * 4 + 2 + r] = pad;
    }
}

// ---------------- aggregation for layers 1..3 (128B rows) -----------------
__global__ __launch_bounds__(256) void k_agg(
    const float* __restrict__ h_in, float* __restrict__ agg_out,
    const float* __restrict__ eps_p, int layer)
{
    float epsv = 1.0f + eps_p[layer];
    ull epsv2; PACKX2(epsv2, epsv, epsv);

    int tid = threadIdx.x, lane = tid & 31, wid = tid >> 5;
    int g = lane >> 3;               // node sub-index 0..3
    int r = lane & 7;                // 16B slot within 128B row
    int w  = blockIdx.x * (blockDim.x >> 5) + wid;
    int nw = gridDim.x * (blockDim.x >> 5);

    const ulonglong2* hin2 = (const ulonglong2*)h_in;
    ulonglong2* agg2 = (ulonglong2*)agg_out;

    for (int tile = w; tile < NN / 4; tile += nw) {
        int i = tile * 4 + g;
        int bo = __ldg(&g_boff[i >> 10]);
        int le = g_cursor[i];
        int ls = (i & 1023) ? g_cursor[i - 1] : 0;
        int start = bo + ls;
        int deg = le - ls;

        int md = deg;
#pragma unroll
        for (int off = 16; off >= 8; off >>= 1)
            md = max(md, __shfl_xor_sync(FULLM, md, off));

        ull A0 = 0ull, A1 = 0ull, B0 = 0ull, B1 = 0ull;
        for (int j = 0; j < md; j += 2) {
            bool p0 = (j < deg), p1 = (j + 1 < deg);
            int s0 = 0, s1 = 0;
            if (p0) s0 = __ldg(&g_csr[start + j]);
            if (p1) s1 = __ldg(&g_csr[start + j + 1]);
            ull v0x = 0ull, v0y = 0ull, v1x = 0ull, v1y = 0ull;
            if (p0) { ulonglong2 v = __ldg(&hin2[s0 * 8 + r]); v0x = v.x; v0y = v.y; }
            if (p1) { ulonglong2 v = __ldg(&hin2[s1 * 8 + r]); v1x = v.x; v1y = v.y; }
            ADDX2(A0, A0, v0x); ADDX2(A1, A1, v0y);
            ADDX2(B0, B0, v1x); ADDX2(B1, B1, v1y);
        }
        ADDX2(A0, A0, B0);
        ADDX2(A1, A1, B1);
        ulonglong2 sf = __ldg(&hin2[i * 8 + r]);
        FMAX2(A0, sf.x, epsv2, A0);
        FMAX2(A1, sf.y, epsv2, A1);
        ulonglong2 res; res.x = A0; res.y = A1;
        agg2[i * 8 + r] = res;
    }
}

// ---------------- MLP + BN stats: z = relu(agg@W1+b1)@W2+b2 -----------------
// SMEM weights (low reg pressure) + 4-node blocking: each weight-pair LDS
// feeds 4 nodes -> smem wavefronts per node cut 4x vs R16.
template <int STRIDE>
__global__ __launch_bounds__(256) void k_mlp(
    const float* __restrict__ agg, float* __restrict__ z_out,
    const float* __restrict__ W1, int w1rows, const float* __restrict__ b1,
    const float* __restrict__ W2, const float* __restrict__ b2,
    float* __restrict__ stats)
{
    constexpr int NP1 = STRIDE / 2;        // W1 pairs
    __shared__ ull w1s[NP1 * 32];
    __shared__ ull w2s[16 * 32];
    __shared__ float b1s[32], b2s[32];
    __shared__ __align__(16) float hs[8][4][32];
    __shared__ float rs[8][32], rq[8][32];

    int tid = threadIdx.x;
    int lane = tid & 31, wid = tid >> 5;

    for (int p = tid; p < NP1 * 32; p += 256) {
        int q = p >> 5, l = p & 31;
        float a = (2 * q     < w1rows) ? __ldg(&W1[(2 * q) * 32 + l])     : 0.f;
        float b = (2 * q + 1 < w1rows) ? __ldg(&W1[(2 * q + 1) * 32 + l]) : 0.f;
        ull pk; PACKX2(pk, a, b);
        w1s[p] = pk;
    }
    for (int p = tid; p < 16 * 32; p += 256) {
        int q = p >> 5, l = p & 31;
        float a = __ldg(&W2[(2 * q) * 32 + l]);
        float b = __ldg(&W2[(2 * q + 1) * 32 + l]);
        ull pk; PACKX2(pk, a, b);
        w2s[p] = pk;
    }
    if (tid < 32) { b1s[tid] = __ldg(&b1[tid]); b2s[tid] = __ldg(&b2[tid]); }
    __syncthreads();

    float b1v = b1s[lane];
    float b2v = b2s[lane];

    int w  = blockIdx.x * 8 + wid;
    int nw = gridDim.x * 8;
    float ssum = 0.f, ssq = 0.f;

    const ulonglong2* agg2 = (const ulonglong2*)agg;

    for (int t = w; t < NN / 4; t += nw) {
        int i0 = t * 4;
        ull hp0[4], hp1[4];
#pragma unroll
        for (int k = 0; k < 4; k++) { hp0[k] = 0ull; hp1[k] = 0ull; }
#pragma unroll
        for (int q = 0; q < STRIDE / 4; q++) {
            ull wA = w1s[(2 * q) * 32 + lane];
            ull wB = w1s[(2 * q + 1) * 32 + lane];
#pragma unroll
            for (int k = 0; k < 4; k++) {
                ulonglong2 a = __ldg(&agg2[(i0 + k) * (STRIDE / 4) + q]);
                FMAX2(hp0[k], a.x, wA, hp0[k]);
                FMAX2(hp1[k], a.y, wB, hp1[k]);
            }
        }
#pragma unroll
        for (int k = 0; k < 4; k++) {
            ADDX2(hp0[k], hp0[k], hp1[k]);
            float lo, hi; UNPACKX2(lo, hi, hp0[k]);
            hs[wid][k][lane] = fmaxf(b1v + lo + hi, 0.f);
        }
        __syncwarp();
        ull op0[4], op1[4];
#pragma unroll
        for (int k = 0; k < 4; k++) { op0[k] = 0ull; op1[k] = 0ull; }
#pragma unroll
        for (int q = 0; q < 8; q++) {
            ull wA = w2s[(2 * q) * 32 + lane];
            ull wB = w2s[(2 * q + 1) * 32 + lane];
#pragma unroll
            for (int k = 0; k < 4; k++) {
                ulonglong2 hq = ((const ulonglong2*)&hs[wid][k][0])[q];
                FMAX2(op0[k], hq.x, wA, op0[k]);
                FMAX2(op1[k], hq.y, wB, op1[k]);
            }
        }
        __syncwarp();
#pragma unroll
        for (int k = 0; k < 4; k++) {
            ADDX2(op0[k], op0[k], op1[k]);
            float ol, oh; UNPACKX2(ol, oh, op0[k]);
            float o = b2v + ol + oh;
            z_out[(i0 + k) * 32 + lane] = o;
            ssum += o;
            ssq  = fmaf(o, o, ssq);
        }
    }

    rs[wid][lane] = ssum;
    rq[wid][lane] = ssq;
    __syncthreads();
    if (wid == 0) {
        float s = 0.f, q = 0.f;
#pragma unroll
        for (int ww = 0; ww < 8; ww++) { s += rs[ww][lane]; q += rq[ww][lane]; }
        atomicAdd(&stats[lane], s);
        atomicAdd(&stats[32 + lane], q);
    }
}

// ---------------- BN apply + ReLU + incremental final linear (layers 0-2) --
__global__ __launch_bounds__(256) void k_bn(
    const float* __restrict__ z, float* __restrict__ h_out,
    const float* __restrict__ gamma, const float* __restrict__ beta,
    const float* __restrict__ linW, const float* __restrict__ lin_b,
    int layer)
{
    __shared__ float sc[32], bi[32];
    __shared__ __align__(16) float hsm[8][32];
    int tid = threadIdx.x;
    int lane = tid & 31, wid = tid >> 5;
    if (tid < 32) {
        float s = g_stats[layer * 64 + tid];
        float q = g_stats[layer * 64 + 32 + tid];
        float mu  = s * (1.0f / NN);
        float var = q * (1.0f / NN) - mu * mu;
        float inv = rsqrtf(var + 1e-5f);
        float g = gamma[layer * 32 + tid] * inv;
        sc[tid] = g;
        bi[tid] = beta[layer * 32 + tid] - mu * g;
    }
    int myd = lane & 7;
    ull lwp[16];
#pragma unroll
    for (int c = 0; c < 32; c += 2) {
        float a = __ldg(&linW[layer * 256 + c * 8 + myd]);
        float b = __ldg(&linW[layer * 256 + (c + 1) * 8 + myd]);
        PACKX2(lwp[c / 2], a, b);
    }
    float lbv = __ldg(&lin_b[myd]);
    __syncthreads();

    int w  = blockIdx.x * (blockDim.x >> 5) + wid;
    int nw = gridDim.x * (blockDim.x >> 5);
    for (int i = w; i < NN; i += nw) {
        float zv = z[i * 32 + lane];
        float h = fmaxf(fmaf(zv, sc[lane], bi[lane]), 0.f);
        h_out[i * 32 + lane] = h;
        hsm[wid][lane] = h;
        __syncwarp();
        ull op0 = 0ull, op1 = 0ull;
        const ulonglong2* hrow = (const ulonglong2*)&hsm[wid][0];
#pragma unroll
        for (int q = 0; q < 8; q++) {
            ulonglong2 hq = hrow[q];
            FMAX2(op0, hq.x, lwp[2 * q + 0], op0);
            FMAX2(op1, hq.y, lwp[2 * q + 1], op1);
        }
        __syncwarp();
        ADDX2(op0, op0, op1);
        float ol, oh; UNPACKX2(ol, oh, op0);
        float v = ol + oh;
        if (lane < 8) {
            if (layer == 0) v += lbv;
            else            v += g_acc[i * 8 + lane];
            g_acc[i * 8 + lane] = v;
        }
    }
}

// ---------------- final BN (layer 3) + masked write-back -------------------
__global__ __launch_bounds__(256) void k_bn_final(
    const float* __restrict__ z,
    const float* __restrict__ gamma, const float* __restrict__ beta,
    const float* __restrict__ linW,
    const float* __restrict__ x,
    const int* __restrict__ nm, const int* __restrict__ em,
    float* __restrict__ out)
{
    const int layer = 3;
    __shared__ float sc[32], bi[32];
    __shared__ __align__(16) float hsm[8][32];
    int tid = threadIdx.x;
    int lane = tid & 31, wid = tid >> 5;
    if (tid < 32) {
        float s = g_stats[layer * 64 + tid];
        float q = g_stats[layer * 64 + 32 + tid];
        float mu  = s * (1.0f / NN);
        float var = q * (1.0f / NN) - mu * mu;
        float inv = rsqrtf(var + 1e-5f);
        float g = gamma[layer * 32 + tid] * inv;
        sc[tid] = g;
        bi[tid] = beta[layer * 32 + tid] - mu * g;
    }
    int myd = lane & 7;
    ull lwp[16];
#pragma unroll
    for (int c = 0; c < 32; c += 2) {
        float a = __ldg(&linW[layer * 256 + c * 8 + myd]);
        float b = __ldg(&linW[layer * 256 + (c + 1) * 8 + myd]);
        PACKX2(lwp[c / 2], a, b);
    }
    __syncthreads();

    int w  = blockIdx.x * (blockDim.x >> 5) + wid;
    int nw = gridDim.x * (blockDim.x >> 5);
    for (int i = w; i < NN; i += nw) {
        float zv = z[i * 32 + lane];
        float h = fmaxf(fmaf(zv, sc[lane], bi[lane]), 0.f);
        hsm[wid][lane] = h;
        __syncwarp();
        ull op0 = 0ull, op1 = 0ull;
        const ulonglong2* hrow = (const ulonglong2*)&hsm[wid][0];
#pragma unroll
        for (int q = 0; q < 8; q++) {
            ulonglong2 hq = hrow[q];
            FMAX2(op0, hq.x, lwp[2 * q + 0], op0);
            FMAX2(op1, hq.y, lwp[2 * q + 1], op1);
        }
        __syncwarp();
        ADDX2(op0, op0, op1);
        float ol, oh; UNPACKX2(ol, oh, op0);
        if (lane < 8) {
            float v = (ol + oh) + g_acc[i * 8 + lane];
            bool n = (nm[i] != 0), e = (em[i] != 0);
            int c = lane;
            bool wr = (c >= 1) && ((c <= 4 && (n || e)) || (c == 5 && n));
            out[i * 8 + c] = wr ? v : __ldg(&x[i * 8 + c]);
        }
    }
}

// ---------------- launch ----------------
extern "C" void kernel_launch(void* const* d_in, const int* in_sizes, int n_in,
                              void* d_out, int out_size)
{
    const float* x        = (const float*)d_in[0];
    const float* t        = (const float*)d_in[1];
    const int*   ei       = (const int*)d_in[2];
    const int*   node_mask = (const int*)d_in[3];
    const int*   edge_mask = (const int*)d_in[4];
    const float* W1_first = (const float*)d_in[7];
    const float* b1_first = (const float*)d_in[8];
    const float* W2_first = (const float*)d_in[9];
    const float* b2_first = (const float*)d_in[10];
    const float* W1_rest  = (const float*)d_in[11];
    const float* b1_rest  = (const float*)d_in[12];
    const float* W2_rest  = (const float*)d_in[13];
    const float* b2_rest  = (const float*)d_in[14];
    const float* eps      = (const float*)d_in[15];
    const float* bn_gamma = (const float*)d_in[16];
    const float* bn_beta  = (const float*)d_in[17];
    const float* lin_W    = (const float*)d_in[18];
    const float* lin_b    = (const float*)d_in[19];
    float* out = (float*)d_out;

    const int GB = 148 * 8;

    float* ag; cudaGetSymbolAddress((void**)&ag, g_agg);
    float* zz; cudaGetSymbolAddress((void**)&zz, g_z);
    float* hA; cudaGetSymbolAddress((void**)&hA, g_hA);
    float* hB; cudaGetSymbolAddress((void**)&hB, g_hB);
    float* st; cudaGetSymbolAddress((void**)&st, g_stats);
    float* sp; cudaGetSymbolAddress((void**)&sp, g_statsP);

    k_hist<<<(EE + 255) / 256, 256>>>(ei);            // #0
    k_scan<<<256, 1024>>>();                          // #1
    k_fill<<<(EE + 255) / 256, 256>>>(ei);            // #2
    // #3 (ncu capture slot): PROBE of the 4-node-blocked k_mlp (stale g_agg,
    // scratch outputs) — verifies the smem-traffic fix in-round.
    k_mlp<32><<<GB, 256>>>(ag, zz, W1_rest + 2 * 1024, 32, b1_rest + 2 * 32,
                           W2_rest + 2 * 1024, b2_rest + 2 * 32, sp);

    // Layer 0
    k_agg0<<<GB, 256>>>(x, ag, eps, t);
    k_mlp<16><<<GB, 256>>>(ag, zz, W1_first, 9, b1_first, W2_first, b2_first, st + 0);
    k_bn<<<GB, 256>>>(zz, hA, bn_gamma, bn_beta, lin_W, lin_b, 0);

    // Layer 1
    k_agg<<<GB, 256>>>(hA, ag, eps, 1);
    k_mlp<32><<<GB, 256>>>(ag, zz, W1_rest + 0 * 1024, 32, b1_rest + 0 * 32,
                           W2_rest + 0 * 1024, b2_rest + 0 * 32, st + 64);
    k_bn<<<GB, 256>>>(zz, hB, bn_gamma, bn_beta, lin_W, lin_b, 1);

    // Layer 2
    k_agg<<<GB, 256>>>(hB, ag, eps, 2);
    k_mlp<32><<<GB, 256>>>(ag, zz, W1_rest + 1 * 1024, 32, b1_rest + 1 * 32,
                           W2_rest + 1 * 1024, b2_rest + 1 * 32, st + 128);
    k_bn<<<GB, 256>>>(zz, hA, bn_gamma, bn_beta, lin_W, lin_b, 2);

    // Layer 3 (bn fused with masked write-back)
    k_agg<<<GB, 256>>>(hA, ag, eps, 3);
    k_mlp<32><<<GB, 256>>>(ag, zz, W1_rest + 2 * 1024, 32, b1_rest + 2 * 32,
                           W2_rest + 2 * 1024, b2_rest + 2 * 32, st + 192);
    k_bn_final<<<GB, 256>>>(zz, bn_gamma, bn_beta, lin_W, x,
                            node_mask, edge_mask, out);
}